// round 8
// baseline (speedup 1.0000x reference)
#include <cuda_runtime.h>

#define G    34
#define NPX  1156            // 34*34
#define ROWS 40              // padded row stride (halo layout)
#define CH   1440            // 36 rows * 40 cols per channel
#define NQ   289             // 17*17 2x2 quads
#define NT   288             // threads per block (9 warps)

typedef unsigned long long ull;

struct Smem {
    ull   wfc1[64 * 12];     // fc1_w duplicated-packed (w,w), [o][k]
    ull   wfc2[64 * 4];      // fc2_w duplicated-packed, [o][c]
    ull   bfc1[64];
    ull   bfc2[4];
    float bufA[4 * CH];      // halo layout, zero borders
    float bufB[4 * CH];
    float scent[NPX];
    float sobx3[NPX];        // sobel-x of scent (constant over steps)
    float soby3[NPX];
    int   hist[256];
    unsigned char maskq[NQ + 3];
    int   s_cl, s_cln, s_z, s_o, s_selbin, s_want;
    float s_red[NT / 32];
    int   s_redi[NT / 32];
};

__device__ __forceinline__ ull pack2(float lo, float hi) {
    ull d; asm("mov.b64 %0, {%1,%2};" : "=l"(d) : "f"(lo), "f"(hi)); return d;
}
__device__ __forceinline__ void unpack2(ull d, float& lo, float& hi) {
    asm("mov.b64 {%0,%1}, %2;" : "=f"(lo), "=f"(hi) : "l"(d));
}
__device__ __forceinline__ ull fma2(ull a, ull b, ull c) {
    ull d; asm("fma.rn.f32x2 %0, %1, %2, %3;" : "=l"(d) : "l"(a), "l"(b), "l"(c)); return d;
}
__device__ __forceinline__ int hidx(int r, int c) { return (r + 1) * ROWS + (c + 2); }

// Load a 4x4 window (rows r0-1..r0+2, cols c0-1..c0+2) from halo-layout channel.
__device__ __forceinline__ void load_win(const float* __restrict__ Cb, float w[4][4]) {
    #pragma unroll
    for (int i = 0; i < 4; ++i) {
        const float* p = Cb + i * ROWS;
        w[i][0] = p[0];
        float2 t = *reinterpret_cast<const float2*>(p + 1);   // 8B aligned by construction
        w[i][1] = t.x; w[i][2] = t.y;
        w[i][3] = p[3];
    }
}

// 4 maxpool3 results (>thr booleans packed in bits 0..3: TL,TR,BL,BR) from a 4x4 window.
__device__ __forceinline__ unsigned mp4(const float w[4][4]) {
    float t0 = fmaxf(w[1][0], w[2][0]), t1 = fmaxf(w[1][1], w[2][1]);
    float t2 = fmaxf(w[1][2], w[2][2]), t3 = fmaxf(w[1][3], w[2][3]);
    float vA0 = fmaxf(t0, w[0][0]), vA1 = fmaxf(t1, w[0][1]);
    float vA2 = fmaxf(t2, w[0][2]), vA3 = fmaxf(t3, w[0][3]);
    float vB0 = fmaxf(t0, w[3][0]), vB1 = fmaxf(t1, w[3][1]);
    float vB2 = fmaxf(t2, w[3][2]), vB3 = fmaxf(t3, w[3][3]);
    float sA = fmaxf(vA1, vA2), sB = fmaxf(vB1, vB2);
    unsigned m = 0;
    m |= (fmaxf(sA, vA0) > 0.1f) ? 1u : 0u;
    m |= (fmaxf(sA, vA3) > 0.1f) ? 2u : 0u;
    m |= (fmaxf(sB, vB0) > 0.1f) ? 4u : 0u;
    m |= (fmaxf(sB, vB3) > 0.1f) ? 8u : 0u;
    return m;
}

__global__ void __launch_bounds__(NT, 2)
ca_kernel(const float* __restrict__ g_cell, const float* __restrict__ g_food,
          const float* __restrict__ g_fc1w, const float* __restrict__ g_fc1b,
          const float* __restrict__ g_fc2w, const float* __restrict__ g_fc2b,
          const float* __restrict__ g_sk, const int* __restrict__ g_steps,
          float* __restrict__ g_out, int B)
{
    extern __shared__ unsigned char dynraw[];
    Smem& sm = *reinterpret_cast<Smem*>(dynraw);
    const int b    = blockIdx.x;
    const int tid  = threadIdx.x;
    const int lane = tid & 31;
    const int wid  = tid >> 5;

    int steps = 32;
    if (g_steps) {
        int s = g_steps[0];
        if (s >= 0 && s <= 100000) steps = s;
    }

    // ---- stage weights ----
    for (int i = tid; i < 64 * 12; i += NT) { float w = g_fc1w[i]; sm.wfc1[i] = pack2(w, w); }
    for (int i = tid; i < 256; i += NT) {
        int c = i >> 6, o = i & 63;
        float w = g_fc2w[i];
        sm.wfc2[o * 4 + c] = pack2(w, w);
    }
    for (int i = tid; i < 64; i += NT) { float w = g_fc1b[i]; sm.bfc1[i] = pack2(w, w); }
    if (tid < 4) { float w = g_fc2b[tid]; sm.bfc2[tid] = pack2(w, w); }
    // zero both buffers (halo must be 0)
    for (int i = tid; i < 4 * CH; i += NT) { sm.bufA[i] = 0.f; sm.bufB[i] = 0.f; }
    if (tid == 0) sm.s_cln = 0;
    __syncthreads();

    // ---- stage food + scent kernel into bufB scratch; load cell interior; init cl ----
    float* f_s = sm.bufB;
    float* k_s = sm.bufB + 1184;
    for (int i = tid; i < NPX; i += NT) f_s[i] = g_food[(size_t)b * NPX + i];
    for (int i = tid; i < 361; i += NT) k_s[i] = g_sk[i];
    {
        int lcl = 0;
        for (int i = tid; i < 4 * NPX; i += NT) {
            int c = i / NPX, p = i - c * NPX;
            int r = p / G, cc = p - r * G;
            float v = g_cell[(size_t)b * 4 * NPX + i];
            sm.bufA[c * CH + hidx(r, cc)] = v;
            if (c == 0) lcl += (v > 0.8f) ? 1 : 0;
        }
        atomicAdd(&sm.s_cln, lcl);
    }
    __syncthreads();

    // ---- scent = conv19x19(food, kernel), zero pad 9 (identical to prior kernel) ----
    for (int i = tid; i < NPX; i += NT) {
        int r = i / G, c = i - r * G;
        float acc = 0.f;
        int u0 = (r - 9 < 0) ? 0 : r - 9, u1 = (r + 9 > G - 1) ? G - 1 : r + 9;
        int v0 = (c - 9 < 0) ? 0 : c - 9, v1 = (c + 9 > G - 1) ? G - 1 : c + 9;
        for (int u = u0; u <= u1; ++u) {
            const float* fr = f_s + u * G;
            const float* kr = k_s + (u - r + 9) * 19 + (9 - c);
            for (int v = v0; v <= v1; ++v) acc += fr[v] * kr[v];
        }
        sm.scent[i] = acc;
    }
    __syncthreads();

    // ---- constant ch3 sobels from scent (identical expression form, zero pad) ----
    for (int i = tid; i < NPX; i += NT) {
        int r = i / G, c = i - r * G;
        float nn[12];
        #pragma unroll
        for (int dr = 0; dr < 3; ++dr) {
            int rr = r + dr - 1;
            #pragma unroll
            for (int dc = 0; dc < 4; ++dc) {
                int cc = c + dc - 1;
                nn[dr * 4 + dc] = (rr >= 0 && rr < G && cc >= 0 && cc < G)
                                      ? sm.scent[rr * G + cc] : 0.f;
            }
        }
        sm.sobx3[i] = ((nn[2] - nn[0]) + 2.f * (nn[6] - nn[4]) + (nn[10] - nn[8])) * 0.125f;
        sm.soby3[i] = ((nn[8] - nn[0]) + 2.f * (nn[9] - nn[1]) + (nn[10] - nn[2])) * 0.125f;
    }
    __syncthreads();
    // re-zero bufB (scratch used its space)
    for (int i = tid; i < 4 * CH; i += NT) sm.bufB[i] = 0.f;
    __syncthreads();

    float* cur = sm.bufA;
    float* nxt = sm.bufB;

    for (int s = 0; s < steps; ++s) {
        const bool last = (s == steps - 1);
        // ---- step head: rotate counters, zero hist ----
        if (tid == 0) { sm.s_cl = sm.s_cln; sm.s_cln = 0; sm.s_z = 0; sm.s_o = 0; }
        if (tid < 256) sm.hist[tid] = 0;

        // ---- Phase B: per-2x2-quad sobel + pre-mask + MLP (2 packed pairs / thread) ----
        for (int q = tid; q < NQ; q += NT) {
            int qr = q / 17, qc = q - qr * 17;
            int r0 = 2 * qr, c0 = 2 * qc;
            int wbase = r0 * ROWS + (c0 + 1);
            ull yT[12], yB[12];
            unsigned pre = 0;
            #pragma unroll
            for (int ch = 0; ch < 3; ++ch) {
                float w[4][4];
                load_win(cur + ch * CH + wbase, w);
                if (ch == 0) pre = mp4(w);
                yT[ch] = pack2(w[1][1], w[1][2]);
                yB[ch] = pack2(w[2][1], w[2][2]);
                yT[4 + ch] = pack2(
                    ((w[0][2] - w[0][0]) + 2.f * (w[1][2] - w[1][0]) + (w[2][2] - w[2][0])) * 0.125f,
                    ((w[0][3] - w[0][1]) + 2.f * (w[1][3] - w[1][1]) + (w[2][3] - w[2][1])) * 0.125f);
                yT[8 + ch] = pack2(
                    ((w[2][0] - w[0][0]) + 2.f * (w[2][1] - w[0][1]) + (w[2][2] - w[0][2])) * 0.125f,
                    ((w[2][1] - w[0][1]) + 2.f * (w[2][2] - w[0][2]) + (w[2][3] - w[0][3])) * 0.125f);
                yB[4 + ch] = pack2(
                    ((w[1][2] - w[1][0]) + 2.f * (w[2][2] - w[2][0]) + (w[3][2] - w[3][0])) * 0.125f,
                    ((w[1][3] - w[1][1]) + 2.f * (w[2][3] - w[2][1]) + (w[3][3] - w[3][1])) * 0.125f);
                yB[8 + ch] = pack2(
                    ((w[3][0] - w[1][0]) + 2.f * (w[3][1] - w[1][1]) + (w[3][2] - w[1][2])) * 0.125f,
                    ((w[3][1] - w[1][1]) + 2.f * (w[3][2] - w[1][2]) + (w[3][3] - w[1][3])) * 0.125f);
            }
            sm.maskq[q] = (unsigned char)pre;
            // ch3: constant scent / sobels
            int pT = r0 * G + c0, pB = pT + G;
            {
                float2 a = *reinterpret_cast<const float2*>(sm.scent + pT);
                float2 bb = *reinterpret_cast<const float2*>(sm.scent + pB);
                yT[3] = pack2(a.x, a.y); yB[3] = pack2(bb.x, bb.y);
                a  = *reinterpret_cast<const float2*>(sm.sobx3 + pT);
                bb = *reinterpret_cast<const float2*>(sm.sobx3 + pB);
                yT[7] = pack2(a.x, a.y); yB[7] = pack2(bb.x, bb.y);
                a  = *reinterpret_cast<const float2*>(sm.soby3 + pT);
                bb = *reinterpret_cast<const float2*>(sm.soby3 + pB);
                yT[11] = pack2(a.x, a.y); yB[11] = pack2(bb.x, bb.y);
            }
            // MLP: fc1(relu) -> fc2, two pixel-pairs share every weight load
            ull uT0 = sm.bfc2[0], uT1 = sm.bfc2[1], uT2 = sm.bfc2[2], uT3 = sm.bfc2[3];
            ull uB0 = uT0, uB1 = uT1, uB2 = uT2, uB3 = uT3;
            #pragma unroll 4
            for (int o = 0; o < 64; ++o) {
                ull hT = sm.bfc1[o], hB = hT;
                const ulonglong2* wp = reinterpret_cast<const ulonglong2*>(sm.wfc1 + o * 12);
                #pragma unroll
                for (int kk = 0; kk < 6; ++kk) {
                    ulonglong2 ww = wp[kk];
                    hT = fma2(yT[2 * kk],     ww.x, hT);
                    hB = fma2(yB[2 * kk],     ww.x, hB);
                    hT = fma2(yT[2 * kk + 1], ww.y, hT);
                    hB = fma2(yB[2 * kk + 1], ww.y, hB);
                }
                float hl, hh;
                unpack2(hT, hl, hh); hT = pack2(fmaxf(hl, 0.f), fmaxf(hh, 0.f));
                unpack2(hB, hl, hh); hB = pack2(fmaxf(hl, 0.f), fmaxf(hh, 0.f));
                const ulonglong2* w2 = reinterpret_cast<const ulonglong2*>(sm.wfc2 + o * 4);
                ulonglong2 wa = w2[0], wb = w2[1];
                uT0 = fma2(hT, wa.x, uT0);  uB0 = fma2(hB, wa.x, uB0);
                uT1 = fma2(hT, wa.y, uT1);  uB1 = fma2(hB, wa.y, uB1);
                uT2 = fma2(hT, wb.x, uT2);  uB2 = fma2(hB, wb.x, uB2);
                uT3 = fma2(hT, wb.y, uT3);  uB3 = fma2(hB, wb.y, uB3);
            }
            int aT = hidx(r0, c0), aB = aT + ROWS;
            float cl_, cr_, ul, ur;
            unpack2(yT[0], cl_, cr_); unpack2(uT0, ul, ur);
            *reinterpret_cast<float2*>(nxt + aT) = make_float2(cl_ + ul, cr_ + ur);
            unpack2(yB[0], cl_, cr_); unpack2(uB0, ul, ur);
            *reinterpret_cast<float2*>(nxt + aB) = make_float2(cl_ + ul, cr_ + ur);
            unpack2(yT[1], cl_, cr_); unpack2(uT1, ul, ur);
            *reinterpret_cast<float2*>(nxt + CH + aT) = make_float2(cl_ + ul, cr_ + ur);
            unpack2(yB[1], cl_, cr_); unpack2(uB1, ul, ur);
            *reinterpret_cast<float2*>(nxt + CH + aB) = make_float2(cl_ + ul, cr_ + ur);
            unpack2(yT[2], cl_, cr_); unpack2(uT2, ul, ur);
            *reinterpret_cast<float2*>(nxt + 2 * CH + aT) = make_float2(cl_ + ul, cr_ + ur);
            unpack2(yB[2], cl_, cr_); unpack2(uB2, ul, ur);
            *reinterpret_cast<float2*>(nxt + 2 * CH + aB) = make_float2(cl_ + ul, cr_ + ur);
            if (last) {
                unpack2(yT[3], cl_, cr_); unpack2(uT3, ul, ur);
                *reinterpret_cast<float2*>(nxt + 3 * CH + aT) = make_float2(cl_ + ul, cr_ + ur);
                unpack2(yB[3], cl_, cr_); unpack2(uB3, ul, ur);
                *reinterpret_cast<float2*>(nxt + 3 * CH + aB) = make_float2(cl_ + ul, cr_ + ur);
            }
        }
        __syncthreads();

        // ---- Phase C1: post-mask from raw nxt ch0; combine with pre-mask ----
        for (int q = tid; q < NQ; q += NT) {
            int qr = q / 17, qc = q - qr * 17;
            int r0 = 2 * qr, c0 = 2 * qc;
            float w[4][4];
            load_win(nxt + r0 * ROWS + (c0 + 1), w);
            sm.maskq[q] = (unsigned char)(sm.maskq[q] & mp4(w));
        }
        __syncthreads();

        // ---- Phase C2: apply mask, clip, count zeros/ones, hist pass 0 ----
        {
            int lz = 0, lo = 0;
            for (int q = tid; q < NQ; q += NT) {
                int qr = q / 17, qc = q - qr * 17;
                int r0 = 2 * qr, c0 = 2 * qc;
                unsigned m = sm.maskq[q];
                int aT = hidx(r0, c0), aB = aT + ROWS;
                const int nch = last ? 4 : 3;
                for (int ch = 0; ch < nch; ++ch) {
                    float* base = nxt + ch * CH;
                    float2 xt = *reinterpret_cast<const float2*>(base + aT);
                    float2 xb = *reinterpret_cast<const float2*>(base + aB);
                    float v0 = (m & 1u) ? xt.x : 0.f;
                    float v1 = (m & 2u) ? xt.y : 0.f;
                    float v2 = (m & 4u) ? xb.x : 0.f;
                    float v3 = (m & 8u) ? xb.y : 0.f;
                    v0 = fminf(fmaxf(v0, -10.f), 10.f);
                    v1 = fminf(fmaxf(v1, -10.f), 10.f);
                    v2 = fminf(fmaxf(v2, -10.f), 10.f);
                    v3 = fminf(fmaxf(v3, -10.f), 10.f);
                    if (ch == 0) {
                        v0 = fminf(fmaxf(v0, 0.f), 1.f);
                        v1 = fminf(fmaxf(v1, 0.f), 1.f);
                        v2 = fminf(fmaxf(v2, 0.f), 1.f);
                        v3 = fminf(fmaxf(v3, 0.f), 1.f);
                        lz += (v0 == 0.f) + (v1 == 0.f) + (v2 == 0.f) + (v3 == 0.f);
                        lo += (v0 == 1.f) + (v1 == 1.f) + (v2 == 1.f) + (v3 == 1.f);
                        if (v0 > 0.f && v0 < 1.f) atomicAdd(&sm.hist[__float_as_uint(v0) >> 24], 1);
                        if (v1 > 0.f && v1 < 1.f) atomicAdd(&sm.hist[__float_as_uint(v1) >> 24], 1);
                        if (v2 > 0.f && v2 < 1.f) atomicAdd(&sm.hist[__float_as_uint(v2) >> 24], 1);
                        if (v3 > 0.f && v3 < 1.f) atomicAdd(&sm.hist[__float_as_uint(v3) >> 24], 1);
                    }
                    *reinterpret_cast<float2*>(base + aT) = make_float2(v0, v1);
                    *reinterpret_cast<float2*>(base + aB) = make_float2(v2, v3);
                }
            }
            atomicAdd(&sm.s_z, lz);
            atomicAdd(&sm.s_o, lo);
        }
        __syncthreads();

        // ---- Selection: kth = ascending_sorted[min(cl, NPX-1)], exact ----
        int want = sm.s_cl; if (want > NPX - 1) want = NPX - 1;
        const int nz = sm.s_z, no = sm.s_o;
        float kth;
        if (want < nz) {
            kth = 0.f;
        } else if (want >= NPX - no) {
            kth = 1.0f;
        } else {
            want -= nz;
            unsigned int prefix = 0;
            for (int pass = 0; pass < 4; ++pass) {
                int shift = 24 - 8 * pass;
                if (pass > 0) {
                    for (int bb = tid; bb < 256; bb += NT) sm.hist[bb] = 0;
                    __syncthreads();
                    for (int i = tid; i < NPX; i += NT) {
                        int r = i / G, c = i - r * G;
                        float v = nxt[(r + 1) * ROWS + c + 2];
                        if (v > 0.f && v < 1.f) {
                            unsigned int bits = __float_as_uint(v);
                            if ((bits >> (shift + 8)) == prefix)
                                atomicAdd(&sm.hist[(bits >> shift) & 255], 1);
                        }
                    }
                    __syncthreads();
                }
                if (tid < 32) {
                    int h[8]; int ssum = 0;
                    #pragma unroll
                    for (int j = 0; j < 8; ++j) { h[j] = sm.hist[tid * 8 + j]; ssum += h[j]; }
                    int inc = ssum;
                    #pragma unroll
                    for (int off = 1; off < 32; off <<= 1) {
                        int t = __shfl_up_sync(0xffffffffu, inc, off);
                        if (lane >= off) inc += t;
                    }
                    int excl = inc - ssum;
                    if (want >= excl && want < excl + ssum) {
                        int w = want - excl;
                        int bsel = 0;
                        while (w >= h[bsel]) { w -= h[bsel]; ++bsel; }
                        sm.s_selbin = tid * 8 + bsel;
                        sm.s_want   = w;
                    }
                }
                __syncthreads();
                prefix = (prefix << 8) | (unsigned int)sm.s_selbin;
                want = sm.s_want;
            }
            kth = __uint_as_float(prefix);
        }

        // ---- Phase D: keep ch0 strictly > kth; count next step's cl ----
        {
            int lcl = 0;
            for (int i = tid; i < NPX; i += NT) {
                int r = i / G, c = i - r * G;
                int idx = (r + 1) * ROWS + c + 2;
                float v = nxt[idx];
                if (v > kth) lcl += (v > 0.8f) ? 1 : 0;
                else nxt[idx] = 0.f;
            }
            atomicAdd(&sm.s_cln, lcl);
        }
        __syncthreads();

        float* t = cur; cur = nxt; nxt = t;
    }

    // ---- outputs: [cell | food | total_pixel_val | living_count] ----
    float* fin = cur;
    const size_t outCell = (size_t)b * 4 * NPX;
    for (int i = tid; i < 4 * NPX; i += NT) {
        int c = i / NPX, p = i - c * NPX;
        int r = p / G, cc = p - r * G;
        g_out[outCell + i] = fin[c * CH + (r + 1) * ROWS + cc + 2];
    }
    const size_t foodBase = (size_t)B * 4 * NPX;
    for (int i = tid; i < NPX; i += NT)
        g_out[foodBase + (size_t)b * NPX + i] = g_food[(size_t)b * NPX + i];

    float lt = 0.f; int lv = 0;
    for (int i = tid; i < NPX; i += NT) {
        int r = i / G, c = i - r * G;
        float v = fin[(r + 1) * ROWS + c + 2];
        lt += v;
        lv += (v > 0.1f) ? 1 : 0;
    }
    #pragma unroll
    for (int off = 16; off; off >>= 1) {
        lt += __shfl_down_sync(0xffffffffu, lt, off);
        lv += __shfl_down_sync(0xffffffffu, lv, off);
    }
    if (lane == 0) { sm.s_red[wid] = lt; sm.s_redi[wid] = lv; }
    __syncthreads();
    if (tid == 0) {
        float T = 0.f; int L = 0;
        #pragma unroll
        for (int w = 0; w < NT / 32; ++w) { T += sm.s_red[w]; L += sm.s_redi[w]; }
        size_t tBase = foodBase + (size_t)B * NPX;
        g_out[tBase + b]     = T;
        g_out[tBase + B + b] = (float)L;
    }
}

extern "C" void kernel_launch(void* const* d_in, const int* in_sizes, int n_in,
                              void* d_out, int out_size) {
    (void)out_size;
    const float* cell  = (const float*)d_in[0];
    const float* food  = (const float*)d_in[1];
    const float* fc1w  = (const float*)d_in[2];
    const float* fc1b  = (const float*)d_in[3];
    const float* fc2w  = (const float*)d_in[4];
    const float* fc2b  = (const float*)d_in[5];
    const float* sk    = (const float*)d_in[6];
    const int*   steps = (n_in >= 8) ? (const int*)d_in[7] : nullptr;

    int B = in_sizes[0] / (4 * NPX);
    size_t smem = sizeof(Smem);
    cudaFuncSetAttribute(ca_kernel, cudaFuncAttributeMaxDynamicSharedMemorySize, (int)smem);
    ca_kernel<<<B, NT, smem>>>(cell, food, fc1w, fc1b, fc2w, fc2b, sk, steps,
                               (float*)d_out, B);
}

// round 9
// speedup vs baseline: 1.2270x; 1.2270x over previous
#include <cuda_runtime.h>

#define G    34
#define NPX  1156            // 34*34
#define ROWS 40              // padded row stride: 3 | 34 | 3
#define CH   1440            // 36 rows * 40 cols
#define NQ   289             // 17*17 2x2 quads
#define NT   320             // 10 warps

typedef unsigned long long ull;

struct Smem {
    ull   wfc1[64 * 12];
    ull   wfc2[64 * 4];
    ull   bfc1[64];
    ull   bfc2[4];
    float state[4 * CH];     // persistent state, halo = 0
    float raw[CH];           // raw ch0 scratch, halo = 0
    float scent[NPX];
    float sobx[NPX];
    float soby[NPX];
    float fscr[NPX];         // food scratch (init only)
    float kscr[364];         // 19x19 kernel scratch (init only)
    int   hist[4][256];
    int   s_cl, s_cln, s_z, s_o, s_selbin, s_want;
    float s_red[NT / 32];
    int   s_redi[NT / 32];
};

__device__ __forceinline__ ull pack2(float lo, float hi) {
    ull d; asm("mov.b64 %0, {%1,%2};" : "=l"(d) : "f"(lo), "f"(hi)); return d;
}
__device__ __forceinline__ void unpack2(ull d, float& lo, float& hi) {
    asm("mov.b64 {%0,%1}, %2;" : "=f"(lo), "=f"(hi) : "l"(d));
}
__device__ __forceinline__ ull fma2(ull a, ull b, ull c) {
    ull d; asm("fma.rn.f32x2 %0, %1, %2, %3;" : "=l"(d) : "l"(a), "l"(b), "l"(c)); return d;
}
__device__ __forceinline__ ull ld2u(const float* p) {
    float2 t = *reinterpret_cast<const float2*>(p);
    return pack2(t.x, t.y);
}
__device__ __forceinline__ int hidx(int r, int c) { return (r + 1) * ROWS + (c + 3); }

// 4x4 window, rows r0-1..r0+2, cols c0-1..c0+2; base = buf + r0*ROWS + c0 + 2 (8B aligned)
__device__ __forceinline__ void load_win2(const float* __restrict__ p, float w[4][4]) {
    #pragma unroll
    for (int i = 0; i < 4; ++i) {
        float2 a = *reinterpret_cast<const float2*>(p + i * ROWS);
        float2 b = *reinterpret_cast<const float2*>(p + i * ROWS + 2);
        w[i][0] = a.x; w[i][1] = a.y; w[i][2] = b.x; w[i][3] = b.y;
    }
}

// 4 maxpool3(>0.1) booleans packed bits 0..3 = TL,TR,BL,BR (zero-halo equiv to -inf: 0<=0.1)
__device__ __forceinline__ unsigned mp4(const float w[4][4]) {
    float t0 = fmaxf(w[1][0], w[2][0]), t1 = fmaxf(w[1][1], w[2][1]);
    float t2 = fmaxf(w[1][2], w[2][2]), t3 = fmaxf(w[1][3], w[2][3]);
    float vA0 = fmaxf(t0, w[0][0]), vA1 = fmaxf(t1, w[0][1]);
    float vA2 = fmaxf(t2, w[0][2]), vA3 = fmaxf(t3, w[0][3]);
    float vB0 = fmaxf(t0, w[3][0]), vB1 = fmaxf(t1, w[3][1]);
    float vB2 = fmaxf(t2, w[3][2]), vB3 = fmaxf(t3, w[3][3]);
    float sA = fmaxf(vA1, vA2), sB = fmaxf(vB1, vB2);
    unsigned m = 0;
    m |= (fmaxf(sA, vA0) > 0.1f) ? 1u : 0u;
    m |= (fmaxf(sA, vA3) > 0.1f) ? 2u : 0u;
    m |= (fmaxf(sB, vB0) > 0.1f) ? 4u : 0u;
    m |= (fmaxf(sB, vB3) > 0.1f) ? 8u : 0u;
    return m;
}

template<bool LAST>
__device__ __forceinline__ void do_step(Smem& sm, int tid, int lane)
{
    const bool act = tid < NQ;
    int r0 = 0, c0 = 0, wb = 0, aT = 0, aB = 0;
    if (act) {
        int qr = tid / 17, qc = tid - qr * 17;
        r0 = 2 * qr; c0 = 2 * qc;
        wb = r0 * ROWS + c0 + 2;
        aT = (r0 + 1) * ROWS + (c0 + 3); aB = aT + ROWS;
    }

    // ---- step head: rotate counters, zero all 4 hists (visible after endB barrier) ----
    if (tid == 0) { sm.s_cl = sm.s_cln; sm.s_cln = 0; sm.s_z = 0; sm.s_o = 0; }
    {
        int* hb = &sm.hist[0][0];
        #pragma unroll
        for (int i = tid; i < 1024; i += NT) hb[i] = 0;
    }

    // ---- Phase B: sobel + pre-mask + MLP per 2x2 quad ----
    unsigned pre = 0;
    float2 xT1, xB1, xT2, xB2;    // raw ch1/ch2 held in registers across the barrier
    if (act) {
        ull yT[12], yB[12];
        #pragma unroll
        for (int ch = 0; ch < 3; ++ch) {
            float w[4][4];
            load_win2(sm.state + ch * CH + wb, w);
            if (ch == 0) pre = mp4(w);
            yT[ch] = pack2(w[1][1], w[1][2]);
            yB[ch] = pack2(w[2][1], w[2][2]);
            yT[4 + ch] = pack2(
                ((w[0][2] - w[0][0]) + 2.f * (w[1][2] - w[1][0]) + (w[2][2] - w[2][0])) * 0.125f,
                ((w[0][3] - w[0][1]) + 2.f * (w[1][3] - w[1][1]) + (w[2][3] - w[2][1])) * 0.125f);
            yT[8 + ch] = pack2(
                ((w[2][0] - w[0][0]) + 2.f * (w[2][1] - w[0][1]) + (w[2][2] - w[0][2])) * 0.125f,
                ((w[2][1] - w[0][1]) + 2.f * (w[2][2] - w[0][2]) + (w[2][3] - w[0][3])) * 0.125f);
            yB[4 + ch] = pack2(
                ((w[1][2] - w[1][0]) + 2.f * (w[2][2] - w[2][0]) + (w[3][2] - w[3][0])) * 0.125f,
                ((w[1][3] - w[1][1]) + 2.f * (w[2][3] - w[2][1]) + (w[3][3] - w[3][1])) * 0.125f);
            yB[8 + ch] = pack2(
                ((w[3][0] - w[1][0]) + 2.f * (w[3][1] - w[1][1]) + (w[3][2] - w[1][2])) * 0.125f,
                ((w[3][1] - w[1][1]) + 2.f * (w[3][2] - w[1][2]) + (w[3][3] - w[1][3])) * 0.125f);
        }
        {
            int pf = r0 * G + c0;
            yT[3]  = ld2u(sm.scent + pf); yB[3]  = ld2u(sm.scent + pf + G);
            yT[7]  = ld2u(sm.sobx + pf);  yB[7]  = ld2u(sm.sobx + pf + G);
            yT[11] = ld2u(sm.soby + pf);  yB[11] = ld2u(sm.soby + pf + G);
        }
        ull uT0 = sm.bfc2[0], uT1 = sm.bfc2[1], uT2 = sm.bfc2[2], uT3 = sm.bfc2[3];
        ull uB0 = uT0, uB1 = uT1, uB2 = uT2, uB3 = uT3;
        #pragma unroll 4
        for (int o = 0; o < 64; ++o) {
            ull hT = sm.bfc1[o], hB = hT;
            const ulonglong2* wp = reinterpret_cast<const ulonglong2*>(sm.wfc1 + o * 12);
            #pragma unroll
            for (int kk = 0; kk < 6; ++kk) {
                ulonglong2 ww = wp[kk];
                hT = fma2(yT[2 * kk],     ww.x, hT);
                hB = fma2(yB[2 * kk],     ww.x, hB);
                hT = fma2(yT[2 * kk + 1], ww.y, hT);
                hB = fma2(yB[2 * kk + 1], ww.y, hB);
            }
            float hl, hh;
            unpack2(hT, hl, hh); hT = pack2(fmaxf(hl, 0.f), fmaxf(hh, 0.f));
            unpack2(hB, hl, hh); hB = pack2(fmaxf(hl, 0.f), fmaxf(hh, 0.f));
            const ulonglong2* w2 = reinterpret_cast<const ulonglong2*>(sm.wfc2 + o * 4);
            ulonglong2 wa = w2[0], wb2 = w2[1];
            uT0 = fma2(hT, wa.x, uT0);   uB0 = fma2(hB, wa.x, uB0);
            uT1 = fma2(hT, wa.y, uT1);   uB1 = fma2(hB, wa.y, uB1);
            uT2 = fma2(hT, wb2.x, uT2);  uB2 = fma2(hB, wb2.x, uB2);
            if (LAST) { uT3 = fma2(hT, wb2.y, uT3); uB3 = fma2(hB, wb2.y, uB3); }
        }
        float cl_, cr_, ul, ur;
        unpack2(yT[0], cl_, cr_); unpack2(uT0, ul, ur);
        sm.raw[aT] = cl_ + ul;  sm.raw[aT + 1] = cr_ + ur;
        unpack2(yB[0], cl_, cr_); unpack2(uB0, ul, ur);
        sm.raw[aB] = cl_ + ul;  sm.raw[aB + 1] = cr_ + ur;
        unpack2(yT[1], cl_, cr_); unpack2(uT1, ul, ur); xT1 = make_float2(cl_ + ul, cr_ + ur);
        unpack2(yB[1], cl_, cr_); unpack2(uB1, ul, ur); xB1 = make_float2(cl_ + ul, cr_ + ur);
        unpack2(yT[2], cl_, cr_); unpack2(uT2, ul, ur); xT2 = make_float2(cl_ + ul, cr_ + ur);
        unpack2(yB[2], cl_, cr_); unpack2(uB2, ul, ur); xB2 = make_float2(cl_ + ul, cr_ + ur);
        if (LAST) {
            float* p3 = sm.state + 3 * CH;
            unpack2(yT[3], cl_, cr_); unpack2(uT3, ul, ur);
            p3[aT] = cl_ + ul;  p3[aT + 1] = cr_ + ur;
            unpack2(yB[3], cl_, cr_); unpack2(uB3, ul, ur);
            p3[aB] = cl_ + ul;  p3[aB + 1] = cr_ + ur;
        }
    }
    __syncthreads();   // endB

    // ---- Phase C (fused): post-mask, apply mask, clip, counts + hist pass0 ----
    float v[4] = {0.f, 0.f, 0.f, 0.f};
    unsigned lz = 0, lo = 0;
    if (act) {
        float w[4][4];
        load_win2(sm.raw + wb, w);
        unsigned m = pre & mp4(w);
        float rv0 = w[1][1], rv1 = w[1][2], rv2 = w[2][1], rv3 = w[2][2];
        float x0 = (m & 1u) ? rv0 : 0.f, x1 = (m & 2u) ? rv1 : 0.f;
        float x2 = (m & 4u) ? rv2 : 0.f, x3 = (m & 8u) ? rv3 : 0.f;
        x0 = fminf(fmaxf(x0, -10.f), 10.f); x1 = fminf(fmaxf(x1, -10.f), 10.f);
        x2 = fminf(fmaxf(x2, -10.f), 10.f); x3 = fminf(fmaxf(x3, -10.f), 10.f);
        x0 = fminf(fmaxf(x0, 0.f), 1.f);    x1 = fminf(fmaxf(x1, 0.f), 1.f);
        x2 = fminf(fmaxf(x2, 0.f), 1.f);    x3 = fminf(fmaxf(x3, 0.f), 1.f);
        v[0] = x0; v[1] = x1; v[2] = x2; v[3] = x3;
        lz = (x0 == 0.f) + (x1 == 0.f) + (x2 == 0.f) + (x3 == 0.f);
        lo = (x0 == 1.f) + (x1 == 1.f) + (x2 == 1.f) + (x3 == 1.f);
        if (x0 > 0.f && x0 < 1.f) atomicAdd(&sm.hist[0][__float_as_uint(x0) >> 24], 1);
        if (x1 > 0.f && x1 < 1.f) atomicAdd(&sm.hist[0][__float_as_uint(x1) >> 24], 1);
        if (x2 > 0.f && x2 < 1.f) atomicAdd(&sm.hist[0][__float_as_uint(x2) >> 24], 1);
        if (x3 > 0.f && x3 < 1.f) atomicAdd(&sm.hist[0][__float_as_uint(x3) >> 24], 1);
        sm.state[aT] = x0; sm.state[aT + 1] = x1;
        sm.state[aB] = x2; sm.state[aB + 1] = x3;
        // ch1
        {
            float a0 = (m & 1u) ? xT1.x : 0.f, a1 = (m & 2u) ? xT1.y : 0.f;
            float a2 = (m & 4u) ? xB1.x : 0.f, a3 = (m & 8u) ? xB1.y : 0.f;
            float* p = sm.state + CH;
            p[aT]     = fminf(fmaxf(a0, -10.f), 10.f);
            p[aT + 1] = fminf(fmaxf(a1, -10.f), 10.f);
            p[aB]     = fminf(fmaxf(a2, -10.f), 10.f);
            p[aB + 1] = fminf(fmaxf(a3, -10.f), 10.f);
        }
        // ch2
        {
            float a0 = (m & 1u) ? xT2.x : 0.f, a1 = (m & 2u) ? xT2.y : 0.f;
            float a2 = (m & 4u) ? xB2.x : 0.f, a3 = (m & 8u) ? xB2.y : 0.f;
            float* p = sm.state + 2 * CH;
            p[aT]     = fminf(fmaxf(a0, -10.f), 10.f);
            p[aT + 1] = fminf(fmaxf(a1, -10.f), 10.f);
            p[aB]     = fminf(fmaxf(a2, -10.f), 10.f);
            p[aB + 1] = fminf(fmaxf(a3, -10.f), 10.f);
        }
        if (LAST) {
            float* p = sm.state + 3 * CH;
            float a0 = (m & 1u) ? p[aT] : 0.f,     a1 = (m & 2u) ? p[aT + 1] : 0.f;
            float a2 = (m & 4u) ? p[aB] : 0.f,     a3 = (m & 8u) ? p[aB + 1] : 0.f;
            p[aT]     = fminf(fmaxf(a0, -10.f), 10.f);
            p[aT + 1] = fminf(fmaxf(a1, -10.f), 10.f);
            p[aB]     = fminf(fmaxf(a2, -10.f), 10.f);
            p[aB + 1] = fminf(fmaxf(a3, -10.f), 10.f);
        }
    }
    lz = __reduce_add_sync(0xffffffffu, lz);
    lo = __reduce_add_sync(0xffffffffu, lo);
    if (lane == 0) { atomicAdd(&sm.s_z, (int)lz); atomicAdd(&sm.s_o, (int)lo); }
    __syncthreads();   // endC (hist pass0 + counts ready)

    // ---- Selection: kth = ascending_sorted[min(cl, NPX-1)], exact radix over registers ----
    int want = sm.s_cl; if (want > NPX - 1) want = NPX - 1;
    const int nz = sm.s_z, no = sm.s_o;
    float kth;
    if (want < nz) {
        kth = 0.f;
    } else if (want >= NPX - no) {
        kth = 1.0f;
    } else {
        want -= nz;
        unsigned prefix = 0;
        #pragma unroll 1
        for (int pass = 0; pass < 4; ++pass) {
            int shift = 24 - 8 * pass;
            if (pass > 0) {
                if (act) {
                    #pragma unroll
                    for (int j = 0; j < 4; ++j) {
                        float x = v[j];
                        if (x > 0.f && x < 1.f) {
                            unsigned bits = __float_as_uint(x);
                            if ((bits >> (shift + 8)) == prefix)
                                atomicAdd(&sm.hist[pass][(bits >> shift) & 255], 1);
                        }
                    }
                }
                __syncthreads();
            }
            if (tid < 32) {
                int h[8]; int ssum = 0;
                #pragma unroll
                for (int j = 0; j < 8; ++j) { h[j] = sm.hist[pass][tid * 8 + j]; ssum += h[j]; }
                int inc = ssum;
                #pragma unroll
                for (int off = 1; off < 32; off <<= 1) {
                    int t = __shfl_up_sync(0xffffffffu, inc, off);
                    if (lane >= off) inc += t;
                }
                int excl = inc - ssum;
                if (want >= excl && want < excl + ssum) {
                    int w2 = want - excl;
                    int bsel = 0;
                    while (w2 >= h[bsel]) { w2 -= h[bsel]; ++bsel; }
                    sm.s_selbin = tid * 8 + bsel;
                    sm.s_want   = w2;
                }
            }
            __syncthreads();
            prefix = (prefix << 8) | (unsigned)sm.s_selbin;
            want = sm.s_want;
        }
        kth = __uint_as_float(prefix);
    }

    // ---- Phase D: keep ch0 strictly > kth (from registers); count next cl ----
    unsigned lcl = 0;
    if (act) {
        if (v[0] > kth) lcl += (v[0] > 0.8f); else sm.state[aT]     = 0.f;
        if (v[1] > kth) lcl += (v[1] > 0.8f); else sm.state[aT + 1] = 0.f;
        if (v[2] > kth) lcl += (v[2] > 0.8f); else sm.state[aB]     = 0.f;
        if (v[3] > kth) lcl += (v[3] > 0.8f); else sm.state[aB + 1] = 0.f;
    }
    lcl = __reduce_add_sync(0xffffffffu, lcl);
    if (lane == 0) atomicAdd(&sm.s_cln, (int)lcl);
    __syncthreads();   // endD
}

__global__ void __launch_bounds__(NT, 2)
ca_kernel(const float* __restrict__ g_cell, const float* __restrict__ g_food,
          const float* __restrict__ g_fc1w, const float* __restrict__ g_fc1b,
          const float* __restrict__ g_fc2w, const float* __restrict__ g_fc2b,
          const float* __restrict__ g_sk, const int* __restrict__ g_steps,
          float* __restrict__ g_out, int B)
{
    extern __shared__ unsigned char dynraw[];
    Smem& sm = *reinterpret_cast<Smem*>(dynraw);
    const int b    = blockIdx.x;
    const int tid  = threadIdx.x;
    const int lane = tid & 31;
    const int wid  = tid >> 5;

    int steps = 32;
    if (g_steps) {
        int s = g_steps[0];
        if (s >= 0 && s <= 100000) steps = s;
    }

    // ---- stage weights ----
    for (int i = tid; i < 64 * 12; i += NT) { float w = g_fc1w[i]; sm.wfc1[i] = pack2(w, w); }
    for (int i = tid; i < 256; i += NT) {
        int c = i >> 6, o = i & 63;
        float w = g_fc2w[i];
        sm.wfc2[o * 4 + c] = pack2(w, w);
    }
    for (int i = tid; i < 64; i += NT) { float w = g_fc1b[i]; sm.bfc1[i] = pack2(w, w); }
    if (tid < 4) { float w = g_fc2b[tid]; sm.bfc2[tid] = pack2(w, w); }
    // zero state + raw (halos must stay 0)
    for (int i = tid; i < 4 * CH; i += NT) sm.state[i] = 0.f;
    for (int i = tid; i < CH; i += NT) sm.raw[i] = 0.f;
    if (tid == 0) sm.s_cln = 0;
    // food + scent kernel scratch
    for (int i = tid; i < NPX; i += NT) sm.fscr[i] = g_food[(size_t)b * NPX + i];
    for (int i = tid; i < 361; i += NT) sm.kscr[i] = g_sk[i];
    __syncthreads();

    // ---- load cell into halo layout; count initial cl ----
    {
        unsigned lcl = 0;
        for (int i = tid; i < 4 * NPX; i += NT) {
            int c = i / NPX, p = i - c * NPX;
            int r = p / G, cc = p - r * G;
            float val = g_cell[(size_t)b * 4 * NPX + i];
            sm.state[c * CH + hidx(r, cc)] = val;
            if (c == 0) lcl += (val > 0.8f) ? 1u : 0u;
        }
        lcl = __reduce_add_sync(0xffffffffu, lcl);
        if (lane == 0) atomicAdd(&sm.s_cln, (int)lcl);
    }
    __syncthreads();

    // ---- scent = conv19x19(food), zero pad 9 ----
    for (int i = tid; i < NPX; i += NT) {
        int r = i / G, c = i - r * G;
        float acc = 0.f;
        int u0 = (r - 9 < 0) ? 0 : r - 9, u1 = (r + 9 > G - 1) ? G - 1 : r + 9;
        int v0 = (c - 9 < 0) ? 0 : c - 9, v1 = (c + 9 > G - 1) ? G - 1 : c + 9;
        for (int u = u0; u <= u1; ++u) {
            const float* fr = sm.fscr + u * G;
            const float* kr = sm.kscr + (u - r + 9) * 19 + (9 - c);
            for (int vv = v0; vv <= v1; ++vv) acc += fr[vv] * kr[vv];
        }
        sm.scent[i] = acc;
    }
    __syncthreads();

    // ---- constant sobels of scent ----
    for (int i = tid; i < NPX; i += NT) {
        int r = i / G, c = i - r * G;
        float nn[12];
        #pragma unroll
        for (int dr = 0; dr < 3; ++dr) {
            int rr = r + dr - 1;
            #pragma unroll
            for (int dc = 0; dc < 4; ++dc) {
                int cc = c + dc - 1;
                nn[dr * 4 + dc] = (rr >= 0 && rr < G && cc >= 0 && cc < G)
                                      ? sm.scent[rr * G + cc] : 0.f;
            }
        }
        sm.sobx[i] = ((nn[2] - nn[0]) + 2.f * (nn[6] - nn[4]) + (nn[10] - nn[8])) * 0.125f;
        sm.soby[i] = ((nn[8] - nn[0]) + 2.f * (nn[9] - nn[1]) + (nn[10] - nn[2])) * 0.125f;
    }
    __syncthreads();

    // ---- main loop ----
    for (int s = 0; s < steps; ++s) {
        if (s == steps - 1) do_step<true>(sm, tid, lane);
        else                do_step<false>(sm, tid, lane);
    }

    // ---- outputs: [cell | food | total_pixel_val | living_count] ----
    const size_t outCell = (size_t)b * 4 * NPX;
    for (int i = tid; i < 4 * NPX; i += NT) {
        int c = i / NPX, p = i - c * NPX;
        int r = p / G, cc = p - r * G;
        g_out[outCell + i] = sm.state[c * CH + hidx(r, cc)];
    }
    const size_t foodBase = (size_t)B * 4 * NPX;
    for (int i = tid; i < NPX; i += NT)
        g_out[foodBase + (size_t)b * NPX + i] = g_food[(size_t)b * NPX + i];

    float lt = 0.f; int lv = 0;
    for (int i = tid; i < NPX; i += NT) {
        int r = i / G, c = i - r * G;
        float x = sm.state[hidx(r, c)];
        lt += x;
        lv += (x > 0.1f) ? 1 : 0;
    }
    #pragma unroll
    for (int off = 16; off; off >>= 1) {
        lt += __shfl_down_sync(0xffffffffu, lt, off);
        lv += __shfl_down_sync(0xffffffffu, lv, off);
    }
    if (lane == 0) { sm.s_red[wid] = lt; sm.s_redi[wid] = lv; }
    __syncthreads();
    if (tid == 0) {
        float T = 0.f; int L = 0;
        #pragma unroll
        for (int w = 0; w < NT / 32; ++w) { T += sm.s_red[w]; L += sm.s_redi[w]; }
        size_t tBase = foodBase + (size_t)B * NPX;
        g_out[tBase + b]     = T;
        g_out[tBase + B + b] = (float)L;
    }
}

extern "C" void kernel_launch(void* const* d_in, const int* in_sizes, int n_in,
                              void* d_out, int out_size) {
    (void)out_size;
    const float* cell  = (const float*)d_in[0];
    const float* food  = (const float*)d_in[1];
    const float* fc1w  = (const float*)d_in[2];
    const float* fc1b  = (const float*)d_in[3];
    const float* fc2w  = (const float*)d_in[4];
    const float* fc2b  = (const float*)d_in[5];
    const float* sk    = (const float*)d_in[6];
    const int*   steps = (n_in >= 8) ? (const int*)d_in[7] : nullptr;

    int B = in_sizes[0] / (4 * NPX);
    size_t smem = sizeof(Smem);
    cudaFuncSetAttribute(ca_kernel, cudaFuncAttributeMaxDynamicSharedMemorySize, (int)smem);
    ca_kernel<<<B, NT, smem>>>(cell, food, fc1w, fc1b, fc2w, fc2b, sk, steps,
                               (float*)d_out, B);
}